// round 6
// baseline (speedup 1.0000x reference)
#include <cuda_runtime.h>
#include <cuda_bf16.h>
#include <cstdint>
#include <math.h>

#define B     64
#define T     256
#define U     1024
#define G3    3072
#define NBLK  128
#define NT    256

// ---- static device scratch ----
// h packed in MMA A-fragment order:
// [par][ (bt*64 + kk)*2 + half ][ lane ] -> uint4 = {a0,a1,a2,a3}
//   bt = batch-tile (16 batches), kk = k-tile (16 k), half: 0=hi,1=lo
__device__ __align__(16) uint4 g_hpk[2][4 * 64 * 2 * 32];
__device__ unsigned g_bar_cnt;
__device__ unsigned g_bar_gen;

// ---- SMEM layout (bytes) ----
// W: [2 pass][24 n][1032 k] bf16
#define SM_W     0
#define W_NSTR   2064
#define W_PSTR   49536
#define SM_REC   99072               // float [2 plane][64][26]
#define REC_PF   1664                // floats per plane
#define SMEM_TOTAL (99072 + 2*6656)  // 112384

// ---- PTX helpers ----
__device__ __forceinline__ uint32_t smem_u32(const void* p) {
    uint32_t a;
    asm("{ .reg .u64 t; cvta.to.shared.u64 t, %1; cvt.u32.u64 %0, t; }" : "=r"(a) : "l"(p));
    return a;
}
__device__ __forceinline__ void ldsm2(uint32_t* r, uint32_t addr) {
    asm volatile("ldmatrix.sync.aligned.m8n8.x2.shared.b16 {%0,%1}, [%2];"
                 : "=r"(r[0]), "=r"(r[1]) : "r"(addr));
}
__device__ __forceinline__ void mma4(float* c, const uint4& a, uint32_t b0, uint32_t b1) {
    asm volatile("mma.sync.aligned.m16n8k16.row.col.f32.bf16.bf16.f32 "
                 "{%0,%1,%2,%3}, {%4,%5,%6,%7}, {%8,%9}, {%0,%1,%2,%3};"
                 : "+f"(c[0]), "+f"(c[1]), "+f"(c[2]), "+f"(c[3])
                 : "r"(a.x), "r"(a.y), "r"(a.z), "r"(a.w), "r"(b0), "r"(b1));
}

// ---- grid barrier (all NBLK CTAs co-resident) ----
__device__ __forceinline__ void grid_barrier() {
    __syncthreads();
    if (threadIdx.x == 0) {
        unsigned gen0;
        asm volatile("ld.acquire.gpu.u32 %0, [%1];" : "=r"(gen0) : "l"(&g_bar_gen));
        unsigned prev;
        asm volatile("atom.release.gpu.global.add.u32 %0, [%1], 1;" : "=r"(prev) : "l"(&g_bar_cnt));
        if (prev == NBLK - 1) {
            asm volatile("st.relaxed.gpu.global.u32 [%0], 0;" :: "l"(&g_bar_cnt));
            asm volatile("red.release.gpu.global.add.u32 [%0], 1;" :: "l"(&g_bar_gen));
        } else {
            unsigned g;
            do { asm volatile("ld.acquire.gpu.u32 %0, [%1];" : "=r"(g) : "l"(&g_bar_gen)); } while (g == gen0);
        }
    }
    __syncthreads();
}

// pack a thread's (b, uu0..uu0+1) h values (hi+lo bf16 pairs) into g_hpk[buf]
__device__ __forceinline__ void pack_h(int buf, int b, int up, int u0, float2 hn) {
    __nv_bfloat16 h0 = __float2bfloat16(hn.x);
    __nv_bfloat16 h1 = __float2bfloat16(hn.y);
    __nv_bfloat16 l0 = __float2bfloat16(hn.x - __bfloat162float(h0));
    __nv_bfloat16 l1 = __float2bfloat16(hn.y - __bfloat162float(h1));
    uint32_t hip = (uint32_t)__bfloat16_as_ushort(h0) | ((uint32_t)__bfloat16_as_ushort(h1) << 16);
    uint32_t lop = (uint32_t)__bfloat16_as_ushort(l0) | ((uint32_t)__bfloat16_as_ushort(l1) << 16);
    int bt = b >> 4, kk = u0 >> 4;
    int r  = b & 15;
    int lane = (r & 7) * 4 + up;
    int reg  = ((r >> 3) & 1) + (((u0 >> 3) & 1) << 1);
    uint32_t* dst = (uint32_t*)(g_hpk[buf] + (size_t)((bt * 64 + kk) * 2) * 32 + lane) + reg;
    *dst = hip;           // hi half-block
    *(dst + 128) = lop;   // lo half-block (+512B)
}

__device__ __forceinline__ float2 sigm2(float2 a) {
    float2 r; r.x = 1.f / (1.f + expf(-a.x)); r.y = 1.f / (1.f + expf(-a.y)); return r;
}

// ---- persistent HMMA-split GRU, fragment-packed h exchange ----
__global__ void __launch_bounds__(NT, 1)
gru_all(const int* __restrict__ x, const float* __restrict__ hidden,
        const float* __restrict__ Win, const float* __restrict__ Wrec,
        const float* __restrict__ bin, const float* __restrict__ brec,
        float* __restrict__ out) {
    extern __shared__ __align__(1024) char smem[];
    const uint32_t sbase = smem_u32(smem);
    float* rec_s = (float*)(smem + SM_REC);
    const int tid = threadIdx.x;
    const int wid = tid >> 5;
    const int l   = tid & 31;
    const int u0  = blockIdx.x * 8;

    // ---- one-time: W_rec slice -> bf16 hi/lo in SMEM [pass][n][k] ----
    for (int idx = tid; idx < 24 * U; idx += NT) {
        int k = idx / 24;
        int j = idx - k * 24;
        int gate = j >> 3, uu = j & 7;
        float w = Wrec[(size_t)k * G3 + gate * U + u0 + uu];
        __nv_bfloat16 hi = __float2bfloat16(w);
        __nv_bfloat16 lo = __float2bfloat16(w - __bfloat162float(hi));
        *(__nv_bfloat16*)(smem + SM_W + j * W_NSTR + k * 2) = hi;
        *(__nv_bfloat16*)(smem + SM_W + W_PSTR + j * W_NSTR + k * 2) = lo;
    }

    // ---- per-thread gate mapping: (b, uu0=2*up, uu0+1) ----
    const int b  = tid >> 2;
    const int up = tid & 3;
    const int uu0 = up * 2;

    float2 bi[3], br[3];
    #pragma unroll
    for (int g = 0; g < 3; g++) {
        bi[g] = *(const float2*)&bin[g * U + u0 + uu0];
        br[g] = *(const float2*)&brec[g * U + u0 + uu0];
    }
    float2 hold = *(const float2*)&hidden[b * U + u0 + uu0];
    pack_h(0, b, up, u0, hold);
    int tok = x[b * T + 0];
    grid_barrier();

    // ---- warp MMA mapping ----
    const int bt = wid & 3;           // batch tile (16 batches)
    const int kh = wid >> 2;          // k half (32 k-tiles)
    const uint32_t boff = (uint32_t)(l & 7) * W_NSTR + (l & 8) * 2;
    const int blk0 = (bt * 64 + kh * 32) * 2;

    for (int t = 0; t < T; t++) {
        const int par = t & 1;

        // gate-input loads (latency hidden behind GEMM)
        float2 xw0 = *(const float2*)&Win[(size_t)tok * G3 + 0 * U + u0 + uu0];
        float2 xw1 = *(const float2*)&Win[(size_t)tok * G3 + 1 * U + u0 + uu0];
        float2 xw2 = *(const float2*)&Win[(size_t)tok * G3 + 2 * U + u0 + uu0];
        int tok_n = (t + 1 < T) ? x[b * T + t + 1] : 0;

        // ---- GEMM: 32 k-tiles, distance-2 prefetched A frags from L2 ----
        const uint4* base = g_hpk[par] + (size_t)blk0 * 32 + l;
        float acc[3][4];
        #pragma unroll
        for (int nt = 0; nt < 3; nt++)
            #pragma unroll
            for (int e = 0; e < 4; e++) acc[nt][e] = 0.f;

        uint4 Ah[2], Al[2];
        Ah[0] = __ldcg(base);       Al[0] = __ldcg(base + 32);
        Ah[1] = __ldcg(base + 64);  Al[1] = __ldcg(base + 96);

        #pragma unroll
        for (int kkl = 0; kkl < 32; kkl++) {
            uint4 ch = Ah[kkl & 1], cl = Al[kkl & 1];
            if (kkl < 30) {
                const uint4* p = base + (kkl + 2) * 64;
                Ah[kkl & 1] = __ldcg(p);
                Al[kkl & 1] = __ldcg(p + 32);
            }
            uint32_t kgb = (uint32_t)(kh * 32 + kkl) * 32;
            #pragma unroll
            for (int nt = 0; nt < 3; nt++) {
                uint32_t bb = sbase + SM_W + nt * 8 * W_NSTR + boff + kgb;
                uint32_t bh[2], bl[2];
                ldsm2(bh, bb);
                ldsm2(bl, bb + W_PSTR);
                mma4(acc[nt], ch, bh[0], bh[1]);   // h_hi @ W_hi
                mma4(acc[nt], ch, bl[0], bl[1]);   // h_hi @ W_lo
                mma4(acc[nt], cl, bh[0], bh[1]);   // h_lo @ W_hi
            }
        }

        // ---- epilogue: write this warp's rec partials to its plane ----
        {
            int bb0 = bt * 16 + (l >> 2);
            float* pl = rec_s + kh * REC_PF;
            #pragma unroll
            for (int nt = 0; nt < 3; nt++) {
                int j0 = nt * 8 + (l & 3) * 2;
                *(float2*)&pl[bb0 * 26 + j0]       = make_float2(acc[nt][0], acc[nt][1]);
                *(float2*)&pl[(bb0 + 8) * 26 + j0] = make_float2(acc[nt][2], acc[nt][3]);
            }
        }
        __syncthreads();

        // ---- gates: 2 units per thread ----
        {
            float2 r0a = *(float2*)&rec_s[b * 26 + 0 + uu0];
            float2 r1a = *(float2*)&rec_s[b * 26 + 8 + uu0];
            float2 r2a = *(float2*)&rec_s[b * 26 + 16 + uu0];
            float2 r0b = *(float2*)&rec_s[REC_PF + b * 26 + 0 + uu0];
            float2 r1b = *(float2*)&rec_s[REC_PF + b * 26 + 8 + uu0];
            float2 r2b = *(float2*)&rec_s[REC_PF + b * 26 + 16 + uu0];

            float2 az, ar, ah;
            az.x = xw0.x + bi[0].x + r0a.x + r0b.x + br[0].x;
            az.y = xw0.y + bi[0].y + r0a.y + r0b.y + br[0].y;
            ar.x = xw1.x + bi[1].x + r1a.x + r1b.x + br[1].x;
            ar.y = xw1.y + bi[1].y + r1a.y + r1b.y + br[1].y;
            ah.x = xw2.x + bi[2].x;
            ah.y = xw2.y + bi[2].y;
            float rhx = r2a.x + r2b.x + br[2].x;
            float rhy = r2a.y + r2b.y + br[2].y;

            float2 z = sigm2(az);
            float2 r = sigm2(ar);
            float2 hh;
            hh.x = tanhf(ah.x + r.x * rhx);
            hh.y = tanhf(ah.y + r.y * rhy);
            float2 hn;
            hn.x = z.x * hold.x + (1.f - z.x) * hh.x;
            hn.y = z.y * hold.y + (1.f - z.y) * hh.y;
            hold = hn;

            *(float2*)&out[((size_t)b * T + t) * U + u0 + uu0] = hn;
            if (t == T - 1)
                *(float2*)&out[(size_t)B * T * U + (size_t)b * U + u0 + uu0] = hn;
            pack_h(par ^ 1, b, up, u0, hn);
        }
        tok = tok_n;
        grid_barrier();
    }
}

extern "C" void kernel_launch(void* const* d_in, const int* in_sizes, int n_in,
                              void* d_out, int out_size) {
    const int*   x      = (const int*)d_in[0];
    const float* hidden = (const float*)d_in[1];
    const float* Win    = (const float*)d_in[2];
    const float* Wrec   = (const float*)d_in[3];
    const float* bin    = (const float*)d_in[4];
    const float* brec   = (const float*)d_in[5];
    float* out = (float*)d_out;

    cudaFuncSetAttribute(gru_all, cudaFuncAttributeMaxDynamicSharedMemorySize, SMEM_TOTAL);
    gru_all<<<NBLK, NT, SMEM_TOTAL>>>(x, hidden, Win, Wrec, bin, brec, out);
}

// round 7
// speedup vs baseline: 1.1129x; 1.1129x over previous
#include <cuda_runtime.h>
#include <cuda_bf16.h>
#include <cstdint>
#include <math.h>

#define B     64
#define T     256
#define U     1024
#define G3    3072
#define NBLK  128
#define NT    512

// ---- static device scratch ----
// h packed in MMA A-fragment order:
// [par][ ((bt*64 + kk)*2 + half)*32 + lane ] -> uint4 = {a0,a1,a2,a3}
__device__ __align__(16) uint4 g_hpk[2][4 * 64 * 2 * 32];
__device__ unsigned g_bar_cnt;
__device__ unsigned g_bar_gen;

// ---- SMEM layout (bytes) ----
#define SM_W     0
#define W_NSTR   2064
#define W_PSTR   49536
#define SM_REC   99072               // float [4 plane][64][26]
#define REC_PF   1664                // floats per plane
#define SMEM_TOTAL (99072 + 4*6656) // 125696

// ---- PTX helpers ----
__device__ __forceinline__ uint32_t smem_u32(const void* p) {
    uint32_t a;
    asm("{ .reg .u64 t; cvta.to.shared.u64 t, %1; cvt.u32.u64 %0, t; }" : "=r"(a) : "l"(p));
    return a;
}
__device__ __forceinline__ void ldsm2(uint32_t* r, uint32_t addr) {
    asm volatile("ldmatrix.sync.aligned.m8n8.x2.shared.b16 {%0,%1}, [%2];"
                 : "=r"(r[0]), "=r"(r[1]) : "r"(addr));
}
__device__ __forceinline__ void ldsm4(uint32_t* r, uint32_t addr) {
    asm volatile("ldmatrix.sync.aligned.m8n8.x4.shared.b16 {%0,%1,%2,%3}, [%4];"
                 : "=r"(r[0]), "=r"(r[1]), "=r"(r[2]), "=r"(r[3]) : "r"(addr));
}
__device__ __forceinline__ void mma4(float* c, const uint4& a, uint32_t b0, uint32_t b1) {
    asm volatile("mma.sync.aligned.m16n8k16.row.col.f32.bf16.bf16.f32 "
                 "{%0,%1,%2,%3}, {%4,%5,%6,%7}, {%8,%9}, {%0,%1,%2,%3};"
                 : "+f"(c[0]), "+f"(c[1]), "+f"(c[2]), "+f"(c[3])
                 : "r"(a.x), "r"(a.y), "r"(a.z), "r"(a.w), "r"(b0), "r"(b1));
}

// ---- grid barrier (all NBLK CTAs co-resident) ----
__device__ __forceinline__ void grid_barrier() {
    __syncthreads();
    if (threadIdx.x == 0) {
        unsigned gen0;
        asm volatile("ld.acquire.gpu.u32 %0, [%1];" : "=r"(gen0) : "l"(&g_bar_gen));
        unsigned prev;
        asm volatile("atom.release.gpu.global.add.u32 %0, [%1], 1;" : "=r"(prev) : "l"(&g_bar_cnt));
        if (prev == NBLK - 1) {
            asm volatile("st.relaxed.gpu.global.u32 [%0], 0;" :: "l"(&g_bar_cnt));
            asm volatile("red.release.gpu.global.add.u32 [%0], 1;" :: "l"(&g_bar_gen));
        } else {
            unsigned g;
            do { asm volatile("ld.acquire.gpu.u32 %0, [%1];" : "=r"(g) : "l"(&g_bar_gen)); } while (g == gen0);
        }
    }
    __syncthreads();
}

// pack a thread's (b, uu0..uu0+1) h values (hi+lo bf16 pairs) into g_hpk[buf]
__device__ __forceinline__ void pack_h(int buf, int b, int up, int u0, float2 hn) {
    __nv_bfloat16 h0 = __float2bfloat16(hn.x);
    __nv_bfloat16 h1 = __float2bfloat16(hn.y);
    __nv_bfloat16 l0 = __float2bfloat16(hn.x - __bfloat162float(h0));
    __nv_bfloat16 l1 = __float2bfloat16(hn.y - __bfloat162float(h1));
    uint32_t hip = (uint32_t)__bfloat16_as_ushort(h0) | ((uint32_t)__bfloat16_as_ushort(h1) << 16);
    uint32_t lop = (uint32_t)__bfloat16_as_ushort(l0) | ((uint32_t)__bfloat16_as_ushort(l1) << 16);
    int bt = b >> 4, kk = u0 >> 4;
    int r  = b & 15;
    int lane = (r & 7) * 4 + up;
    int reg  = ((r >> 3) & 1) + (((u0 >> 3) & 1) << 1);
    uint32_t* dst = (uint32_t*)(g_hpk[buf] + (size_t)((bt * 64 + kk) * 2) * 32 + lane) + reg;
    *dst = hip;           // hi half-block
    *(dst + 128) = lop;   // lo half-block (+512B)
}

__device__ __forceinline__ float2 sigm2(float2 a) {
    float2 r; r.x = 1.f / (1.f + expf(-a.x)); r.y = 1.f / (1.f + expf(-a.y)); return r;
}

// ---- persistent HMMA-split GRU: 16 warps, deep A prefetch ----
__global__ void __launch_bounds__(NT, 1)
gru_all(const int* __restrict__ x, const float* __restrict__ hidden,
        const float* __restrict__ Win, const float* __restrict__ Wrec,
        const float* __restrict__ bin, const float* __restrict__ brec,
        float* __restrict__ out) {
    extern __shared__ __align__(1024) char smem[];
    const uint32_t sbase = smem_u32(smem);
    float* rec_s = (float*)(smem + SM_REC);
    const int tid = threadIdx.x;
    const int wid = tid >> 5;
    const int l   = tid & 31;
    const int u0  = blockIdx.x * 8;

    // ---- one-time: W_rec slice -> bf16 hi/lo in SMEM [pass][n][k] ----
    for (int idx = tid; idx < 24 * U; idx += NT) {
        int k = idx / 24;
        int j = idx - k * 24;
        int gate = j >> 3, uu = j & 7;
        float w = Wrec[(size_t)k * G3 + gate * U + u0 + uu];
        __nv_bfloat16 hi = __float2bfloat16(w);
        __nv_bfloat16 lo = __float2bfloat16(w - __bfloat162float(hi));
        *(__nv_bfloat16*)(smem + SM_W + j * W_NSTR + k * 2) = hi;
        *(__nv_bfloat16*)(smem + SM_W + W_PSTR + j * W_NSTR + k * 2) = lo;
    }

    // ---- per-thread gate mapping (threads 0..255): (b, uu0=2*up, uu0+1) ----
    const int b  = tid >> 2;       // valid for tid<256
    const int up = tid & 3;
    const int uu0 = up * 2;

    float2 bi[3], br[3], hold;
    int tok = 0;
    if (tid < 256) {
        #pragma unroll
        for (int g = 0; g < 3; g++) {
            bi[g] = *(const float2*)&bin[g * U + u0 + uu0];
            br[g] = *(const float2*)&brec[g * U + u0 + uu0];
        }
        hold = *(const float2*)&hidden[b * U + u0 + uu0];
        pack_h(0, b, up, u0, hold);
        tok = x[b * T + 0];
    }
    grid_barrier();

    // ---- warp MMA mapping: 4 batch-tiles x 4 k-quarters ----
    const int bt = wid & 3;
    const int kq = wid >> 2;
    // ldsm4: blocks (n0..7,k0..7),(n0..7,k8..15),(n8..15,k0..7),(n8..15,k8..15)
    const uint32_t boff4 = (uint32_t)((l >> 4) * 8 + (l & 7)) * W_NSTR + ((l >> 3) & 1) * 16;
    const uint32_t boff2 = (uint32_t)(l & 7) * W_NSTR + (l & 8) * 2;
    const int blk0 = (bt * 64 + kq * 16) * 2;

    for (int t = 0; t < T; t++) {
        const int par = t & 1;

        // gate-input loads (latency hidden behind GEMM)
        float2 xw0, xw1, xw2;
        int tok_n = 0;
        if (tid < 256) {
            xw0 = *(const float2*)&Win[(size_t)tok * G3 + 0 * U + u0 + uu0];
            xw1 = *(const float2*)&Win[(size_t)tok * G3 + 1 * U + u0 + uu0];
            xw2 = *(const float2*)&Win[(size_t)tok * G3 + 2 * U + u0 + uu0];
            tok_n = (t + 1 < T) ? x[b * T + t + 1] : 0;
        }

        // ---- GEMM: 16 k-tiles/warp, ring-4 prefetch from L2 ----
        const uint4* base = g_hpk[par] + (size_t)blk0 * 32 + l;
        float acc[3][4];
        #pragma unroll
        for (int nt = 0; nt < 3; nt++)
            #pragma unroll
            for (int e = 0; e < 4; e++) acc[nt][e] = 0.f;

        uint4 Ah[4], Al[4];
        #pragma unroll
        for (int i = 0; i < 4; i++) {
            Ah[i] = __ldcg(base + i * 64);
            Al[i] = __ldcg(base + i * 64 + 32);
        }

        #pragma unroll
        for (int kkl = 0; kkl < 16; kkl++) {
            uint4 ch = Ah[kkl & 3], cl = Al[kkl & 3];
            if (kkl < 12) {
                const uint4* p = base + (kkl + 4) * 64;
                Ah[kkl & 3] = __ldcg(p);
                Al[kkl & 3] = __ldcg(p + 32);
            }
            uint32_t kgb = (uint32_t)(kq * 16 + kkl) * 32;
            uint32_t wb = sbase + SM_W + kgb;
            uint32_t bh01[4], bl01[4], bh2[2], bl2[2];
            ldsm4(bh01, wb + boff4);                       // nt0, nt1 (hi)
            ldsm2(bh2,  wb + 16 * W_NSTR + boff2);         // nt2 (hi)
            ldsm4(bl01, wb + W_PSTR + boff4);              // nt0, nt1 (lo)
            ldsm2(bl2,  wb + W_PSTR + 16 * W_NSTR + boff2);// nt2 (lo)

            mma4(acc[0], ch, bh01[0], bh01[1]);
            mma4(acc[1], ch, bh01[2], bh01[3]);
            mma4(acc[2], ch, bh2[0],  bh2[1]);
            mma4(acc[0], ch, bl01[0], bl01[1]);
            mma4(acc[1], ch, bl01[2], bl01[3]);
            mma4(acc[2], ch, bl2[0],  bl2[1]);
            mma4(acc[0], cl, bh01[0], bh01[1]);
            mma4(acc[1], cl, bh01[2], bh01[3]);
            mma4(acc[2], cl, bh2[0],  bh2[1]);
        }

        // ---- epilogue: this warp's partials -> plane kq ----
        {
            int bb0 = bt * 16 + (l >> 2);
            float* pl = rec_s + kq * REC_PF;
            #pragma unroll
            for (int nt = 0; nt < 3; nt++) {
                int j0 = nt * 8 + (l & 3) * 2;
                *(float2*)&pl[bb0 * 26 + j0]       = make_float2(acc[nt][0], acc[nt][1]);
                *(float2*)&pl[(bb0 + 8) * 26 + j0] = make_float2(acc[nt][2], acc[nt][3]);
            }
        }
        __syncthreads();

        // ---- gates: threads 0..255, 2 units each ----
        if (tid < 256) {
            float rz = br[0].x, rzy = br[0].y;
            float rr = br[1].x, rry = br[1].y;
            float rh = br[2].x, rhy = br[2].y;
            #pragma unroll
            for (int p = 0; p < 4; p++) {
                const float* pl = rec_s + p * REC_PF + b * 26;
                float2 a0 = *(const float2*)&pl[0 + uu0];
                float2 a1 = *(const float2*)&pl[8 + uu0];
                float2 a2 = *(const float2*)&pl[16 + uu0];
                rz += a0.x; rzy += a0.y;
                rr += a1.x; rry += a1.y;
                rh += a2.x; rhy += a2.y;
            }
            float2 az, ar, ah;
            az.x = xw0.x + bi[0].x + rz;
            az.y = xw0.y + bi[0].y + rzy;
            ar.x = xw1.x + bi[1].x + rr;
            ar.y = xw1.y + bi[1].y + rry;
            ah.x = xw2.x + bi[2].x;
            ah.y = xw2.y + bi[2].y;

            float2 z = sigm2(az);
            float2 r = sigm2(ar);
            float2 hh;
            hh.x = tanhf(ah.x + r.x * rh);
            hh.y = tanhf(ah.y + r.y * rhy);
            float2 hn;
            hn.x = z.x * hold.x + (1.f - z.x) * hh.x;
            hn.y = z.y * hold.y + (1.f - z.y) * hh.y;
            hold = hn;

            *(float2*)&out[((size_t)b * T + t) * U + u0 + uu0] = hn;
            if (t == T - 1)
                *(float2*)&out[(size_t)B * T * U + (size_t)b * U + u0 + uu0] = hn;
            pack_h(par ^ 1, b, up, u0, hn);
            tok = tok_n;
        }
        grid_barrier();
    }
}

extern "C" void kernel_launch(void* const* d_in, const int* in_sizes, int n_in,
                              void* d_out, int out_size) {
    const int*   x      = (const int*)d_in[0];
    const float* hidden = (const float*)d_in[1];
    const float* Win    = (const float*)d_in[2];
    const float* Wrec   = (const float*)d_in[3];
    const float* bin    = (const float*)d_in[4];
    const float* brec   = (const float*)d_in[5];
    float* out = (float*)d_out;

    cudaFuncSetAttribute(gru_all, cudaFuncAttributeMaxDynamicSharedMemorySize, SMEM_TOTAL);
    gru_all<<<NBLK, NT, SMEM_TOTAL>>>(x, hidden, Win, Wrec, bin, brec, out);
}